// round 5
// baseline (speedup 1.0000x reference)
#include <cuda_runtime.h>

// LIF spike recurrence:
//   x: [T=8, B=32, C=128, H=32, W=32] float32
//   alpha, Vth: scalar float32 (device, 1 element each)
//   out spikes: [T, B, C, H, W] float32
//
// mem_0 = 0
// mem_t = mem_{t-1} * TAU + x_t * alpha
// spike_t = (mem_t - Vth) > 0 ? 1 : 0
// mem_t = (1 - spike_t) * mem_t   (hard reset)
//
// Recurrence only over T -> each thread owns 4 adjacent chains (float4).
// HBM-bound: 67 MB total traffic.

#define TAU 0.5f

static constexpr int T = 8;
static constexpr int N_SPATIAL = 32 * 128 * 32 * 32;  // 1,048,576
static constexpr int N_VEC = N_SPATIAL / 4;           // 262,144 float4 chains

__global__ __launch_bounds__(256) void lif_spike_kernel(
    const float4* __restrict__ x,
    const float* __restrict__ alpha_p,
    const float* __restrict__ vth_p,
    float4* __restrict__ out)
{
    const int i = blockIdx.x * blockDim.x + threadIdx.x;
    if (i >= N_VEC) return;

    const float alpha = __ldg(alpha_p);
    const float vth   = __ldg(vth_p);

    // Front-batch all 8 strided loads for MLP=8 (hide DRAM latency).
    float4 xv[T];
#pragma unroll
    for (int t = 0; t < T; t++) {
        xv[t] = x[(size_t)t * N_VEC + i];
    }

    float4 mem = make_float4(0.f, 0.f, 0.f, 0.f);

#pragma unroll
    for (int t = 0; t < T; t++) {
        mem.x = fmaf(xv[t].x, alpha, mem.x * TAU);
        mem.y = fmaf(xv[t].y, alpha, mem.y * TAU);
        mem.z = fmaf(xv[t].z, alpha, mem.z * TAU);
        mem.w = fmaf(xv[t].w, alpha, mem.w * TAU);

        float4 sp;
        sp.x = (mem.x > vth) ? 1.0f : 0.0f;
        sp.y = (mem.y > vth) ? 1.0f : 0.0f;
        sp.z = (mem.z > vth) ? 1.0f : 0.0f;
        sp.w = (mem.w > vth) ? 1.0f : 0.0f;

        // hard reset
        mem.x = (sp.x > 0.0f) ? 0.0f : mem.x;
        mem.y = (sp.y > 0.0f) ? 0.0f : mem.y;
        mem.z = (sp.z > 0.0f) ? 0.0f : mem.z;
        mem.w = (sp.w > 0.0f) ? 0.0f : mem.w;

        out[(size_t)t * N_VEC + i] = sp;
    }
}

extern "C" void kernel_launch(void* const* d_in, const int* in_sizes, int n_in,
                              void* d_out, int out_size)
{
    const float4* x     = (const float4*)d_in[0];
    const float*  alpha = (const float*)d_in[1];
    const float*  vth   = (const float*)d_in[2];
    float4*       out   = (float4*)d_out;

    const int threads = 256;
    const int blocks = (N_VEC + threads - 1) / threads;  // 1024
    lif_spike_kernel<<<blocks, threads>>>(x, alpha, vth, out);
}

// round 8
// speedup vs baseline: 1.0014x; 1.0014x over previous
#include <cuda_runtime.h>

// LIF spike recurrence:
//   x: [T=8, B=32, C=128, H=32, W=32] float32
//   alpha, Vth: scalar float32 (device, 1 element each)
//   out spikes: [T, B, C, H, W] float32
//
// mem_0 = 0
// mem_t = mem_{t-1} * TAU + x_t * alpha
// spike_t = (mem_t - Vth) > 0 ? 1 : 0
// mem_t = (1 - spike_t) * mem_t   (hard reset)
//
// Recurrence only over T -> each thread owns 4 adjacent chains (float4).
// HBM-bound: 67 MB logical traffic (fits in 126 MB L2 across graph replays).
//
// R5 changes vs R1:
//  - __launch_bounds__(256, 4): allow up to 64 regs so the 8-deep float4
//    load batch stays fully in flight (R1's 32-reg cap serialized the loads,
//    MLP collapsed, issue=17.8%).
//  - __stcs (st.global.cs, evict-first) for spike output: output is never
//    re-read by us, so keep it from thrashing L2 -> x stays L2-resident
//    across timed graph replays.

#define TAU 0.5f

static constexpr int T = 8;
static constexpr int N_SPATIAL = 32 * 128 * 32 * 32;  // 1,048,576
static constexpr int N_VEC = N_SPATIAL / 4;           // 262,144 float4 chains

__global__ __launch_bounds__(256, 4) void lif_spike_kernel(
    const float4* __restrict__ x,
    const float* __restrict__ alpha_p,
    const float* __restrict__ vth_p,
    float4* __restrict__ out)
{
    const int i = blockIdx.x * blockDim.x + threadIdx.x;
    if (i >= N_VEC) return;

    const float alpha = __ldg(alpha_p);
    const float vth   = __ldg(vth_p);

    // Front-batch all 8 strided loads for MLP=8 (hide DRAM latency).
    float4 xv[T];
#pragma unroll
    for (int t = 0; t < T; t++) {
        xv[t] = __ldg(&x[(size_t)t * N_VEC + i]);
    }

    float4 mem = make_float4(0.f, 0.f, 0.f, 0.f);

#pragma unroll
    for (int t = 0; t < T; t++) {
        mem.x = fmaf(xv[t].x, alpha, mem.x * TAU);
        mem.y = fmaf(xv[t].y, alpha, mem.y * TAU);
        mem.z = fmaf(xv[t].z, alpha, mem.z * TAU);
        mem.w = fmaf(xv[t].w, alpha, mem.w * TAU);

        float4 sp;
        sp.x = (mem.x > vth) ? 1.0f : 0.0f;
        sp.y = (mem.y > vth) ? 1.0f : 0.0f;
        sp.z = (mem.z > vth) ? 1.0f : 0.0f;
        sp.w = (mem.w > vth) ? 1.0f : 0.0f;

        // hard reset
        mem.x = (sp.x > 0.0f) ? 0.0f : mem.x;
        mem.y = (sp.y > 0.0f) ? 0.0f : mem.y;
        mem.z = (sp.z > 0.0f) ? 0.0f : mem.z;
        mem.w = (sp.w > 0.0f) ? 0.0f : mem.w;

        // Streaming store: evict-first in L2 so x stays resident across
        // graph replays (output is write-once, never re-read here).
        __stcs(&out[(size_t)t * N_VEC + i], sp);
    }
}

extern "C" void kernel_launch(void* const* d_in, const int* in_sizes, int n_in,
                              void* d_out, int out_size)
{
    const float4* x     = (const float4*)d_in[0];
    const float*  alpha = (const float*)d_in[1];
    const float*  vth   = (const float*)d_in[2];
    float4*       out   = (float4*)d_out;

    const int threads = 256;
    const int blocks = (N_VEC + threads - 1) / threads;  // 1024
    lif_spike_kernel<<<blocks, threads>>>(x, alpha, vth, out);
}